// round 3
// baseline (speedup 1.0000x reference)
#include <cuda_runtime.h>

// ---------------- problem constants ----------------
constexpr int nB = 64, nC = 16, SZ = 128, WS = 32, PS = 8, nH = 8;
constexpr int WN = 4, NWIN = 16, NPAT = 16;
constexpr int PD = 1024, PDH = 128, PLD = 1024, WDH = 128, WINNER = 1024, WD = 16384;
constexpr float EPS = 1e-5f;
constexpr float RSQRT128 = 0.08838834764831845f;

// ---------------- scratch (device globals; no allocs allowed) ------------
// Aliased lifetimes:
//   g_bufA: fl (LN'd patch feats)  -> later pf (patch attn out)      64 MB
//   g_bufB: qk (patch q|k)         -> later pfo (pf @ Wout_p)       128 MB
//   g_bufC: pv (patch v)                                             64 MB
//   g_bufD: xwln (LN'd window)     -> later wfo (wf @ Wout_w)        64 MB
__device__ float g_bufA[(size_t)nB*NWIN*NPAT*PD];
__device__ float g_bufB[(size_t)nB*NWIN*NPAT*2*PD];
__device__ float g_bufC[(size_t)nB*NWIN*NPAT*PD];
__device__ float g_bufD[(size_t)nB*NWIN*WD];
__device__ float g_pl  [(size_t)nB*NWIN*PLD];
__device__ float g_qkw [(size_t)nB*NWIN*2*PLD];
__device__ float g_dsdiag[(size_t)nB*nH*NWIN];
__device__ float g_nds [(size_t)nB*nH*NWIN*NWIN];
__device__ float g_wv  [(size_t)nB*NWIN*WINNER];
__device__ float g_wf  [(size_t)nB*NWIN*WINNER];

// ---------------- block reduction (sum, sumsq) ----------------
__device__ __forceinline__ void blk_reduce_2(float& s, float& s2, float* rbuf) {
    int lane = threadIdx.x & 31, warp = threadIdx.x >> 5;
#pragma unroll
    for (int o = 16; o > 0; o >>= 1) {
        s  += __shfl_down_sync(0xffffffffu, s,  o);
        s2 += __shfl_down_sync(0xffffffffu, s2, o);
    }
    if (lane == 0) { rbuf[warp] = s; rbuf[32 + warp] = s2; }
    __syncthreads();
    int nw = blockDim.x >> 5;
    if (warp == 0) {
        s  = lane < nw ? rbuf[lane]      : 0.f;
        s2 = lane < nw ? rbuf[32 + lane] : 0.f;
#pragma unroll
        for (int o = 16; o > 0; o >>= 1) {
            s  += __shfl_down_sync(0xffffffffu, s,  o);
            s2 += __shfl_down_sync(0xffffffffu, s2, o);
        }
        if (lane == 0) { rbuf[0] = s; rbuf[32] = s2; }
    }
    __syncthreads();
    s = rbuf[0]; s2 = rbuf[32];
}

// ---------------- K1: patch gather + LayerNorm ----------------
// fl[b, win, pat, (sy*8+sx)*16+c] = LN_1024( x[b,c, wy*32+py*8+sy, wx*32+px*8+sx] )
__global__ void k_patch_ln(const float* __restrict__ x,
                           const float* __restrict__ g, const float* __restrict__ bt,
                           float* __restrict__ fl) {
    __shared__ float sv[PD];
    __shared__ float rbuf[64];
    int blk = blockIdx.x;                       // b*256 + win*16 + pat
    int pat = blk & 15, win = (blk >> 4) & 15, b = blk >> 8;
    int wy = win >> 2, wx = win & 3, py = pat >> 2, px = pat & 3;
    int y0 = wy * WS + py * PS, x0 = wx * WS + px * PS;
    int t = threadIdx.x;
    int sx = t & 7, sy = (t >> 3) & 7, c0 = t >> 6;
    float s = 0.f, s2 = 0.f;
#pragma unroll
    for (int ci = 0; ci < 4; ci++) {
        int c = ci * 4 + c0;
        float v = x[((b * nC + c) * SZ + y0 + sy) * SZ + x0 + sx];
        sv[((sy * 8 + sx) << 4) + c] = v;
        s += v; s2 += v * v;
    }
    __syncthreads();
    blk_reduce_2(s, s2, rbuf);
    float mean = s * (1.f / PD);
    float var  = s2 * (1.f / PD) - mean * mean;
    float rstd = rsqrtf(var + EPS);
    float* out = fl + (size_t)blk * PD;
    for (int i = t; i < PD; i += 256) out[i] = (sv[i] - mean) * rstd * g[i] + bt[i];
}

// ---------------- K5: 4x4 avg-pool + gather + LayerNorm ----------------
__global__ void k_pool_ln(const float* __restrict__ x,
                          const float* __restrict__ g, const float* __restrict__ bt,
                          float* __restrict__ plo) {
    __shared__ float sv[PLD];
    __shared__ float rbuf[64];
    int blk = blockIdx.x;                        // b*16 + win
    int win = blk & 15, b = blk >> 4;
    int wy = win >> 2, wx = win & 3;
    int t = threadIdx.x;
    int ix = t & 7, iy = (t >> 3) & 7, c0 = t >> 6;
    float s = 0.f, s2 = 0.f;
#pragma unroll
    for (int ci = 0; ci < 4; ci++) {
        int c = ci * 4 + c0;
        const float* base = x + ((size_t)(b * nC + c) * SZ + wy * WS + iy * 4) * SZ + wx * WS + ix * 4;
        float acc = 0.f;
#pragma unroll
        for (int u = 0; u < 4; u++) {
            float4 v4 = *(const float4*)(base + u * SZ);
            acc += v4.x + v4.y + v4.z + v4.w;
        }
        float v = acc * (1.f / 16.f);
        sv[((iy * 8 + ix) << 4) + c] = v;
        s += v; s2 += v * v;
    }
    __syncthreads();
    blk_reduce_2(s, s2, rbuf);
    float mean = s * (1.f / PLD);
    float var  = s2 * (1.f / PLD) - mean * mean;
    float rstd = rsqrtf(var + EPS);
    float* out = plo + (size_t)blk * PLD;
    for (int i = t; i < PLD; i += 256) out[i] = (sv[i] - mean) * rstd * g[i] + bt[i];
}

// ---------------- K8: window gather + LayerNorm over 16384 ----------------
__global__ void k_xw_ln(const float* __restrict__ x,
                        const float* __restrict__ g, const float* __restrict__ bt,
                        float* __restrict__ xwln) {
    extern __shared__ float sm[];               // 16384 floats (64 KB dynamic)
    __shared__ float rbuf[64];
    int blk = blockIdx.x;                        // b*16 + win
    int win = blk & 15, b = blk >> 4;
    int wy = win >> 2, wx = win & 3;
    int t = threadIdx.x;
    int sx = t & 31, r = t >> 5;
    float s = 0.f, s2 = 0.f;
    for (int c = 0; c < nC; c++) {
#pragma unroll
        for (int q = 0; q < 4; q++) {
            int sy = q * 8 + r;
            float v = x[((size_t)(b * nC + c) * SZ + wy * WS + sy) * SZ + wx * WS + sx];
            sm[((sy * WS + sx) << 4) + c] = v;
            s += v; s2 += v * v;
        }
    }
    __syncthreads();
    blk_reduce_2(s, s2, rbuf);
    float mean = s * (1.f / WD);
    float var  = s2 * (1.f / WD) - mean * mean;
    float rstd = rsqrtf(var + EPS);
    float* out = xwln + (size_t)blk * WD;
    for (int i = t; i < WD; i += 256) out[i] = (sm[i] - mean) * rstd * g[i] + bt[i];
}

// ---------------- tiled fp32 SGEMM: C[M,N] = A[M,K] @ B[K,N], row-major ----------------
template<int BM, int BN, int BK, int TM, int TN>
__global__ void sgemm(const float* __restrict__ A, const float* __restrict__ Bw,
                      float* __restrict__ Cw, int M, int N, int K) {
    constexpr int THREADS = (BM / TM) * (BN / TN);
    __shared__ float As[BK][BM];
    __shared__ float Bs[BK][BN];
    int t = threadIdx.x;
    int tx = t % (BN / TN), ty = t / (BN / TN);
    const float* Ab = A + (size_t)blockIdx.y * BM * K;
    const float* Bb = Bw + (size_t)blockIdx.x * BN;
    float acc[TM][TN] = {};
    for (int k0 = 0; k0 < K; k0 += BK) {
#pragma unroll
        for (int i = t; i < BM * BK / 4; i += THREADS) {
            int row = i / (BK / 4), c4 = i % (BK / 4);
            float4 v = *(const float4*)(Ab + (size_t)row * K + k0 + c4 * 4);
            As[c4 * 4 + 0][row] = v.x; As[c4 * 4 + 1][row] = v.y;
            As[c4 * 4 + 2][row] = v.z; As[c4 * 4 + 3][row] = v.w;
        }
#pragma unroll
        for (int i = t; i < BK * BN / 4; i += THREADS) {
            int row = i / (BN / 4), c4 = i % (BN / 4);
            *(float4*)&Bs[row][c4 * 4] = *(const float4*)(Bb + (size_t)(k0 + row) * N + c4 * 4);
        }
        __syncthreads();
#pragma unroll
        for (int kk = 0; kk < BK; kk++) {
            float ar[TM], br[TN];
#pragma unroll
            for (int m = 0; m < TM; m++) ar[m] = As[kk][ty * TM + m];
#pragma unroll
            for (int n = 0; n < TN; n++) br[n] = Bs[kk][tx * TN + n];
#pragma unroll
            for (int m = 0; m < TM; m++)
#pragma unroll
                for (int n = 0; n < TN; n++) acc[m][n] = fmaf(ar[m], br[n], acc[m][n]);
        }
        __syncthreads();
    }
#pragma unroll
    for (int m = 0; m < TM; m++) {
        float* crow = Cw + (size_t)(blockIdx.y * BM + ty * TM + m) * N + blockIdx.x * BN + tx * TN;
#pragma unroll
        for (int n = 0; n < TN; n += 4)
            *(float4*)(crow + n) = make_float4(acc[m][n], acc[m][n+1], acc[m][n+2], acc[m][n+3]);
    }
}

// ---------------- K3: patch attention (16x16) + LePE conv, per (b,win,head) ----------------
__global__ void k_patch_attn(const float* __restrict__ qkg, const float* __restrict__ pvg,
                             const float* __restrict__ cw, const float* __restrict__ cb,
                             float* __restrict__ pfg) {
    __shared__ float q[16][129], k[16][129], v[16][129];
    __shared__ float p[16][17];
    __shared__ float w9[PDH * 9];
    __shared__ float bi[PDH];
    int h = blockIdx.x & 7;
    int bw = blockIdx.x >> 3;                   // b*16 + win
    int t = threadIdx.x;
    for (int i = t; i < 2048; i += 256) {
        int row = i >> 7, d = i & 127;
        const float* qkb = qkg + ((size_t)bw * 16 + row) * 2048 + h * 128 + d;
        q[row][d] = qkb[0];
        k[row][d] = qkb[1024];
        v[row][d] = pvg[((size_t)bw * 16 + row) * 1024 + h * 128 + d];
    }
    for (int i = t; i < PDH * 9; i += 256) w9[i] = cw[i];
    if (t < PDH) bi[t] = cb[t];
    __syncthreads();
    {
        int i = t >> 4, j = t & 15;
        float s = 0.f;
#pragma unroll 8
        for (int d = 0; d < 128; d++) s = fmaf(q[i][d], k[j][d], s);
        p[i][j] = s * RSQRT128;
    }
    __syncthreads();
    if (t < 16) {
        float m = -1e30f;
        for (int j = 0; j < 16; j++) m = fmaxf(m, p[t][j]);
        float sum = 0.f;
        for (int j = 0; j < 16; j++) { float e = __expf(p[t][j] - m); p[t][j] = e; sum += e; }
        float inv = 1.f / sum;
        for (int j = 0; j < 16; j++) p[t][j] *= inv;
    }
    __syncthreads();
    for (int e = t; e < 2048; e += 256) {
        int i = e >> 7, d = e & 127;
        float acc = 0.f;
#pragma unroll
        for (int j = 0; j < 16; j++) acc = fmaf(p[i][j], v[j][d], acc);
        int py = i >> 2, px = i & 3;
        float ca = bi[d];
#pragma unroll
        for (int dy = -1; dy <= 1; dy++) {
            int ny = py + dy; if (ny < 0 || ny > 3) continue;
#pragma unroll
            for (int dx = -1; dx <= 1; dx++) {
                int nx = px + dx; if (nx < 0 || nx > 3) continue;
                ca = fmaf(w9[d * 9 + (dy + 1) * 3 + (dx + 1)], v[ny * 4 + nx][d], ca);
            }
        }
        pfg[((size_t)bw * 16 + i) * 1024 + h * 128 + d] = acc + ca;
    }
}

// ---------------- K7: window attention probs + diag/nds post-processing ----------------
__global__ void k_win_probs(const float* __restrict__ qkwg) {
    __shared__ float q[16][129], k[16][129], p[16][17];
    int h = blockIdx.x & 7, b = blockIdx.x >> 3;
    int t = threadIdx.x;
    for (int i = t; i < 2048; i += 256) {
        int row = i >> 7, d = i & 127;
        const float* base = qkwg + ((size_t)b * 16 + row) * 2048 + h * 128 + d;
        q[row][d] = base[0];
        k[row][d] = base[1024];
    }
    __syncthreads();
    {
        int i = t >> 4, j = t & 15;
        float s = 0.f;
#pragma unroll 8
        for (int d = 0; d < 128; d++) s = fmaf(q[i][d], k[j][d], s);
        p[i][j] = s * RSQRT128;
    }
    __syncthreads();
    if (t < 16) {
        float m = -1e30f;
        for (int j = 0; j < 16; j++) m = fmaxf(m, p[t][j]);
        float sum = 0.f;
        for (int j = 0; j < 16; j++) { float e = __expf(p[t][j] - m); p[t][j] = e; sum += e; }
        float inv = 1.f / sum;
        for (int j = 0; j < 16; j++) p[t][j] *= inv;
        float diag = p[t][t];
        bool line = diag < 0.5f;
        g_dsdiag[((size_t)b * 8 + h) * 16 + t] = line ? 0.5f : diag;
        float sc = line ? 0.5f / (1.f - diag) : 1.f;
        for (int j = 0; j < 16; j++)
            g_nds[(((size_t)b * 8 + h) * 16 + t) * 16 + j] = (j == t) ? 0.f : p[t][j] * sc;
    }
}

// ---------------- K10: window value mix (nds @ wv) + LePE conv ----------------
__global__ void k_win_val(const float* __restrict__ wvg,
                          const float* __restrict__ cw, const float* __restrict__ cb,
                          float* __restrict__ wfg) {
    __shared__ float v[16][129];
    __shared__ float p[16][17];
    __shared__ float w9[WDH * 9];
    __shared__ float bi[WDH];
    int h = blockIdx.x & 7, b = blockIdx.x >> 3;
    int t = threadIdx.x;
    for (int i = t; i < 2048; i += 256) {
        int row = i >> 7, d = i & 127;
        v[row][d] = wvg[((size_t)b * 16 + row) * 1024 + h * 128 + d];
    }
    p[t >> 4][t & 15] = g_nds[((size_t)b * 8 + h) * 256 + t];
    for (int i = t; i < WDH * 9; i += 256) w9[i] = cw[i];
    if (t < WDH) bi[t] = cb[t];
    __syncthreads();
    for (int e = t; e < 2048; e += 256) {
        int i = e >> 7, d = e & 127;
        float acc = 0.f;
#pragma unroll
        for (int j = 0; j < 16; j++) acc = fmaf(p[i][j], v[j][d], acc);
        int gy = i >> 2, gx = i & 3;
        float ca = bi[d];
#pragma unroll
        for (int dy = -1; dy <= 1; dy++) {
            int ny = gy + dy; if (ny < 0 || ny > 3) continue;
#pragma unroll
            for (int dx = -1; dx <= 1; dx++) {
                int nx = gx + dx; if (nx < 0 || nx > 3) continue;
                ca = fmaf(w9[d * 9 + (dy + 1) * 3 + (dx + 1)], v[ny * 4 + nx][d], ca);
            }
        }
        wfg[((size_t)b * 16 + i) * 1024 + h * 128 + d] = acc + ca;
    }
}

// ---------------- K12: diag-scale + add + inverse shuffle + residual ----------------
__global__ void k_final(const float* __restrict__ x, const float* __restrict__ pfo,
                        const float* __restrict__ wfo, float* __restrict__ out) {
    __shared__ float sa[512], sb[512], sds[8];
    int blk = blockIdx.x;                        // b*512 + win*32 + sy
    int sy = blk & 31, win = (blk >> 5) & 15, b = blk >> 9;
    int wy = win >> 2, wx = win & 3;
    int t = threadIdx.x;
    size_t base = ((size_t)b * 16 + win) * WD + (size_t)sy * 512;
    for (int e = t; e < 512; e += 256) { sa[e] = pfo[base + e]; sb[e] = wfo[base + e]; }
    if (t < 8) sds[t] = g_dsdiag[((size_t)b * 8 + t) * 16 + win];
    __syncthreads();
    int y = wy * WS + sy;
    for (int i = t; i < 512; i += 256) {
        int c = i >> 5, sx = i & 31;
        int e = sx * 16 + c;
        int hh = (sy * 32 + sx) >> 7;
        size_t xi = ((size_t)(b * nC + c) * SZ + y) * SZ + wx * WS + sx;
        out[xi] = x[xi] + sds[hh] * sa[e] + sb[e];
    }
}

// ---------------- launch ----------------
extern "C" void kernel_launch(void* const* d_in, const int* in_sizes, int n_in,
                              void* d_out, int out_size) {
    const float* x        = (const float*)d_in[0];
    const float* pn_g     = (const float*)d_in[1];
    const float* pn_b     = (const float*)d_in[2];
    const float* Wqk_p    = (const float*)d_in[3];
    const float* Wv_p     = (const float*)d_in[4];
    const float* conv_p_w = (const float*)d_in[5];
    const float* conv_p_b = (const float*)d_in[6];
    const float* Wout_p   = (const float*)d_in[7];
    const float* pln_g    = (const float*)d_in[8];
    const float* pln_b    = (const float*)d_in[9];
    const float* Wqk_w    = (const float*)d_in[10];
    const float* wn_g     = (const float*)d_in[11];
    const float* wn_b     = (const float*)d_in[12];
    const float* Wv_w     = (const float*)d_in[13];
    const float* conv_w_w = (const float*)d_in[14];
    const float* conv_w_b = (const float*)d_in[15];
    const float* Wout_w   = (const float*)d_in[16];
    float* out = (float*)d_out;

    float *bufA, *bufB, *bufC, *bufD, *pl, *qkw, *wv, *wf;
    cudaGetSymbolAddress((void**)&bufA, g_bufA);
    cudaGetSymbolAddress((void**)&bufB, g_bufB);
    cudaGetSymbolAddress((void**)&bufC, g_bufC);
    cudaGetSymbolAddress((void**)&bufD, g_bufD);
    cudaGetSymbolAddress((void**)&pl,   g_pl);
    cudaGetSymbolAddress((void**)&qkw,  g_qkw);
    cudaGetSymbolAddress((void**)&wv,   g_wv);
    cudaGetSymbolAddress((void**)&wf,   g_wf);

    // alias map (lifetimes verified):
    float* fl   = bufA;   // LN'd patch feats
    float* qk   = bufB;   // patch q|k (dead after k_patch_attn)
    float* pv   = bufC;
    float* pf   = bufA;   // reuse: fl dead after Wqk/Wv GEMMs
    float* pfo  = bufB;   // reuse: qk dead after k_patch_attn
    float* xwln = bufD;
    float* wfo  = bufD;   // reuse: xwln dead after Wv_w GEMM

    cudaFuncSetAttribute(k_xw_ln, cudaFuncAttributeMaxDynamicSharedMemorySize, WD * 4);

    // ---- patch (intra-window) branch ----
    k_patch_ln<<<nB * NWIN * NPAT, 256>>>(x, pn_g, pn_b, fl);
    sgemm<128,128,16,8,8><<<dim3(2048/128, 16384/128), 256>>>(fl, Wqk_p, qk, 16384, 2048, 1024);
    sgemm<128,128,16,8,8><<<dim3(1024/128, 16384/128), 256>>>(fl, Wv_p,  pv, 16384, 1024, 1024);
    k_patch_attn<<<nB * NWIN * nH, 256>>>(qk, pv, conv_p_w, conv_p_b, pf);
    sgemm<128,128,16,8,8><<<dim3(1024/128, 16384/128), 256>>>(pf, Wout_p, pfo, 16384, 1024, 1024);

    // ---- window (inter-window) branch ----
    k_pool_ln<<<nB * NWIN, 256>>>(x, pln_g, pln_b, pl);
    sgemm<128,128,16,8,8><<<dim3(2048/128, 1024/128), 256>>>(pl, Wqk_w, qkw, 1024, 2048, 1024);
    k_win_probs<<<nB * nH, 256>>>(qkw);
    k_xw_ln<<<nB * NWIN, 256, WD * 4>>>(x, wn_g, wn_b, xwln);
    sgemm<64,64,16,4,4><<<dim3(1024/64, 1024/64), 256>>>(xwln, Wv_w, wv, 1024, 1024, 16384);
    k_win_val<<<nB * nH, 256>>>(wv, conv_w_w, conv_w_b, wf);
    sgemm<128,128,16,8,8><<<dim3(16384/128, 1024/128), 256>>>(wf, Wout_w, wfo, 1024, 16384, 1024);

    // ---- fuse diag-scale + residual + inverse shuffle ----
    k_final<<<nB * NWIN * WS, 256>>>(x, pfo, wfo, out);
}

// round 5
// speedup vs baseline: 1.0012x; 1.0012x over previous
#include <cuda_runtime.h>

// ---------------- problem constants ----------------
constexpr int nB = 64, nC = 16, SZ = 128, WS = 32, PS = 8, nH = 8;
constexpr int WN = 4, NWIN = 16, NPAT = 16;
constexpr int PD = 1024, PDH = 128, PLD = 1024, WDH = 128, WINNER = 1024, WD = 16384;
constexpr float EPS = 1e-5f;
constexpr float RSQRT128 = 0.08838834764831845f;

// ---------------- scratch (device globals; no allocs allowed) ------------
// Aliased lifetimes:
//   g_bufA: fl (LN'd patch feats)  -> later pf (patch attn out)      64 MB
//   g_bufB: qk (patch q|k)         -> later pfo (pf @ Wout_p)       128 MB
//   g_bufC: pv (patch v)                                             64 MB
//   g_bufD: xwln (LN'd window)     -> later wfo (wf @ Wout_w)        64 MB
__device__ float g_bufA[(size_t)nB*NWIN*NPAT*PD];
__device__ float g_bufB[(size_t)nB*NWIN*NPAT*2*PD];
__device__ float g_bufC[(size_t)nB*NWIN*NPAT*PD];
__device__ float g_bufD[(size_t)nB*NWIN*WD];
__device__ float g_pl  [(size_t)nB*NWIN*PLD];
__device__ float g_qkw [(size_t)nB*NWIN*2*PLD];
__device__ float g_dsdiag[(size_t)nB*nH*NWIN];
__device__ float g_nds [(size_t)nB*nH*NWIN*NWIN];
__device__ float g_wv  [(size_t)nB*NWIN*WINNER];
__device__ float g_wf  [(size_t)nB*NWIN*WINNER];

// ---------------- block reduction (sum, sumsq) ----------------
__device__ __forceinline__ void blk_reduce_2(float& s, float& s2, float* rbuf) {
    int lane = threadIdx.x & 31, warp = threadIdx.x >> 5;
#pragma unroll
    for (int o = 16; o > 0; o >>= 1) {
        s  += __shfl_down_sync(0xffffffffu, s,  o);
        s2 += __shfl_down_sync(0xffffffffu, s2, o);
    }
    if (lane == 0) { rbuf[warp] = s; rbuf[32 + warp] = s2; }
    __syncthreads();
    int nw = blockDim.x >> 5;
    if (warp == 0) {
        s  = lane < nw ? rbuf[lane]      : 0.f;
        s2 = lane < nw ? rbuf[32 + lane] : 0.f;
#pragma unroll
        for (int o = 16; o > 0; o >>= 1) {
            s  += __shfl_down_sync(0xffffffffu, s,  o);
            s2 += __shfl_down_sync(0xffffffffu, s2, o);
        }
        if (lane == 0) { rbuf[0] = s; rbuf[32] = s2; }
    }
    __syncthreads();
    s = rbuf[0]; s2 = rbuf[32];
}

// ---------------- K1: patch gather + LayerNorm ----------------
// fl[b, win, pat, (sy*8+sx)*16+c] = LN_1024( x[b,c, wy*32+py*8+sy, wx*32+px*8+sx] )
__global__ void k_patch_ln(const float* __restrict__ x,
                           const float* __restrict__ g, const float* __restrict__ bt,
                           float* __restrict__ fl) {
    __shared__ float sv[PD];
    __shared__ float rbuf[64];
    int blk = blockIdx.x;                       // b*256 + win*16 + pat
    int pat = blk & 15, win = (blk >> 4) & 15, b = blk >> 8;
    int wy = win >> 2, wx = win & 3, py = pat >> 2, px = pat & 3;
    int y0 = wy * WS + py * PS, x0 = wx * WS + px * PS;
    int t = threadIdx.x;
    int sx = t & 7, sy = (t >> 3) & 7, c0 = t >> 6;
    float s = 0.f, s2 = 0.f;
#pragma unroll
    for (int ci = 0; ci < 4; ci++) {
        int c = ci * 4 + c0;
        float v = x[((b * nC + c) * SZ + y0 + sy) * SZ + x0 + sx];
        sv[((sy * 8 + sx) << 4) + c] = v;
        s += v; s2 += v * v;
    }
    __syncthreads();
    blk_reduce_2(s, s2, rbuf);
    float mean = s * (1.f / PD);
    float var  = s2 * (1.f / PD) - mean * mean;
    float rstd = rsqrtf(var + EPS);
    float* out = fl + (size_t)blk * PD;
    for (int i = t; i < PD; i += 256) out[i] = (sv[i] - mean) * rstd * g[i] + bt[i];
}

// ---------------- K5: 4x4 avg-pool + gather + LayerNorm ----------------
__global__ void k_pool_ln(const float* __restrict__ x,
                          const float* __restrict__ g, const float* __restrict__ bt,
                          float* __restrict__ plo) {
    __shared__ float sv[PLD];
    __shared__ float rbuf[64];
    int blk = blockIdx.x;                        // b*16 + win
    int win = blk & 15, b = blk >> 4;
    int wy = win >> 2, wx = win & 3;
    int t = threadIdx.x;
    int ix = t & 7, iy = (t >> 3) & 7, c0 = t >> 6;
    float s = 0.f, s2 = 0.f;
#pragma unroll
    for (int ci = 0; ci < 4; ci++) {
        int c = ci * 4 + c0;
        const float* base = x + ((size_t)(b * nC + c) * SZ + wy * WS + iy * 4) * SZ + wx * WS + ix * 4;
        float acc = 0.f;
#pragma unroll
        for (int u = 0; u < 4; u++) {
            float4 v4 = *(const float4*)(base + u * SZ);
            acc += v4.x + v4.y + v4.z + v4.w;
        }
        float v = acc * (1.f / 16.f);
        sv[((iy * 8 + ix) << 4) + c] = v;
        s += v; s2 += v * v;
    }
    __syncthreads();
    blk_reduce_2(s, s2, rbuf);
    float mean = s * (1.f / PLD);
    float var  = s2 * (1.f / PLD) - mean * mean;
    float rstd = rsqrtf(var + EPS);
    float* out = plo + (size_t)blk * PLD;
    for (int i = t; i < PLD; i += 256) out[i] = (sv[i] - mean) * rstd * g[i] + bt[i];
}

// ---------------- K8: window gather + LayerNorm over 16384 ----------------
__global__ void k_xw_ln(const float* __restrict__ x,
                        const float* __restrict__ g, const float* __restrict__ bt,
                        float* __restrict__ xwln) {
    extern __shared__ float sm[];               // 16384 floats (64 KB dynamic)
    __shared__ float rbuf[64];
    int blk = blockIdx.x;                        // b*16 + win
    int win = blk & 15, b = blk >> 4;
    int wy = win >> 2, wx = win & 3;
    int t = threadIdx.x;
    int sx = t & 31, r = t >> 5;
    float s = 0.f, s2 = 0.f;
    for (int c = 0; c < nC; c++) {
#pragma unroll
        for (int q = 0; q < 4; q++) {
            int sy = q * 8 + r;
            float v = x[((size_t)(b * nC + c) * SZ + wy * WS + sy) * SZ + wx * WS + sx];
            sm[((sy * WS + sx) << 4) + c] = v;
            s += v; s2 += v * v;
        }
    }
    __syncthreads();
    blk_reduce_2(s, s2, rbuf);
    float mean = s * (1.f / WD);
    float var  = s2 * (1.f / WD) - mean * mean;
    float rstd = rsqrtf(var + EPS);
    float* out = xwln + (size_t)blk * WD;
    for (int i = t; i < WD; i += 256) out[i] = (sm[i] - mean) * rstd * g[i] + bt[i];
}

// ---------------- tiled fp32 SGEMM: C[M,N] = A[M,K] @ B[K,N], row-major ----------------
template<int BM, int BN, int BK, int TM, int TN>
__global__ void sgemm(const float* __restrict__ A, const float* __restrict__ Bw,
                      float* __restrict__ Cw, int M, int N, int K) {
    constexpr int THREADS = (BM / TM) * (BN / TN);
    __shared__ float As[BK][BM];
    __shared__ float Bs[BK][BN];
    int t = threadIdx.x;
    int tx = t % (BN / TN), ty = t / (BN / TN);
    const float* Ab = A + (size_t)blockIdx.y * BM * K;
    const float* Bb = Bw + (size_t)blockIdx.x * BN;
    float acc[TM][TN] = {};
    for (int k0 = 0; k0 < K; k0 += BK) {
#pragma unroll
        for (int i = t; i < BM * BK / 4; i += THREADS) {
            int row = i / (BK / 4), c4 = i % (BK / 4);
            float4 v = *(const float4*)(Ab + (size_t)row * K + k0 + c4 * 4);
            As[c4 * 4 + 0][row] = v.x; As[c4 * 4 + 1][row] = v.y;
            As[c4 * 4 + 2][row] = v.z; As[c4 * 4 + 3][row] = v.w;
        }
#pragma unroll
        for (int i = t; i < BK * BN / 4; i += THREADS) {
            int row = i / (BN / 4), c4 = i % (BN / 4);
            *(float4*)&Bs[row][c4 * 4] = *(const float4*)(Bb + (size_t)(k0 + row) * N + c4 * 4);
        }
        __syncthreads();
#pragma unroll
        for (int kk = 0; kk < BK; kk++) {
            float ar[TM], br[TN];
#pragma unroll
            for (int m = 0; m < TM; m++) ar[m] = As[kk][ty * TM + m];
#pragma unroll
            for (int n = 0; n < TN; n++) br[n] = Bs[kk][tx * TN + n];
#pragma unroll
            for (int m = 0; m < TM; m++)
#pragma unroll
                for (int n = 0; n < TN; n++) acc[m][n] = fmaf(ar[m], br[n], acc[m][n]);
        }
        __syncthreads();
    }
#pragma unroll
    for (int m = 0; m < TM; m++) {
        float* crow = Cw + (size_t)(blockIdx.y * BM + ty * TM + m) * N + blockIdx.x * BN + tx * TN;
#pragma unroll
        for (int n = 0; n < TN; n += 4)
            *(float4*)(crow + n) = make_float4(acc[m][n], acc[m][n+1], acc[m][n+2], acc[m][n+3]);
    }
}

// ---------------- K3: patch attention (16x16) + LePE conv, per (b,win,head) ----------------
__global__ void k_patch_attn(const float* __restrict__ qkg, const float* __restrict__ pvg,
                             const float* __restrict__ cw, const float* __restrict__ cb,
                             float* __restrict__ pfg) {
    __shared__ float q[16][129], k[16][129], v[16][129];
    __shared__ float p[16][17];
    __shared__ float w9[PDH * 9];
    __shared__ float bi[PDH];
    int h = blockIdx.x & 7;
    int bw = blockIdx.x >> 3;                   // b*16 + win
    int t = threadIdx.x;
    for (int i = t; i < 2048; i += 256) {
        int row = i >> 7, d = i & 127;
        const float* qkb = qkg + ((size_t)bw * 16 + row) * 2048 + h * 128 + d;
        q[row][d] = qkb[0];
        k[row][d] = qkb[1024];
        v[row][d] = pvg[((size_t)bw * 16 + row) * 1024 + h * 128 + d];
    }
    for (int i = t; i < PDH * 9; i += 256) w9[i] = cw[i];
    if (t < PDH) bi[t] = cb[t];
    __syncthreads();
    {
        int i = t >> 4, j = t & 15;
        float s = 0.f;
#pragma unroll 8
        for (int d = 0; d < 128; d++) s = fmaf(q[i][d], k[j][d], s);
        p[i][j] = s * RSQRT128;
    }
    __syncthreads();
    if (t < 16) {
        float m = -1e30f;
        for (int j = 0; j < 16; j++) m = fmaxf(m, p[t][j]);
        float sum = 0.f;
        for (int j = 0; j < 16; j++) { float e = __expf(p[t][j] - m); p[t][j] = e; sum += e; }
        float inv = 1.f / sum;
        for (int j = 0; j < 16; j++) p[t][j] *= inv;
    }
    __syncthreads();
    for (int e = t; e < 2048; e += 256) {
        int i = e >> 7, d = e & 127;
        float acc = 0.f;
#pragma unroll
        for (int j = 0; j < 16; j++) acc = fmaf(p[i][j], v[j][d], acc);
        int py = i >> 2, px = i & 3;
        float ca = bi[d];
#pragma unroll
        for (int dy = -1; dy <= 1; dy++) {
            int ny = py + dy; if (ny < 0 || ny > 3) continue;
#pragma unroll
            for (int dx = -1; dx <= 1; dx++) {
                int nx = px + dx; if (nx < 0 || nx > 3) continue;
                ca = fmaf(w9[d * 9 + (dy + 1) * 3 + (dx + 1)], v[ny * 4 + nx][d], ca);
            }
        }
        pfg[((size_t)bw * 16 + i) * 1024 + h * 128 + d] = acc + ca;
    }
}

// ---------------- K7: window attention probs + diag/nds post-processing ----------------
__global__ void k_win_probs(const float* __restrict__ qkwg) {
    __shared__ float q[16][129], k[16][129], p[16][17];
    int h = blockIdx.x & 7, b = blockIdx.x >> 3;
    int t = threadIdx.x;
    for (int i = t; i < 2048; i += 256) {
        int row = i >> 7, d = i & 127;
        const float* base = qkwg + ((size_t)b * 16 + row) * 2048 + h * 128 + d;
        q[row][d] = base[0];
        k[row][d] = base[1024];
    }
    __syncthreads();
    {
        int i = t >> 4, j = t & 15;
        float s = 0.f;
#pragma unroll 8
        for (int d = 0; d < 128; d++) s = fmaf(q[i][d], k[j][d], s);
        p[i][j] = s * RSQRT128;
    }
    __syncthreads();
    if (t < 16) {
        float m = -1e30f;
        for (int j = 0; j < 16; j++) m = fmaxf(m, p[t][j]);
        float sum = 0.f;
        for (int j = 0; j < 16; j++) { float e = __expf(p[t][j] - m); p[t][j] = e; sum += e; }
        float inv = 1.f / sum;
        for (int j = 0; j < 16; j++) p[t][j] *= inv;
        float diag = p[t][t];
        bool line = diag < 0.5f;
        g_dsdiag[((size_t)b * 8 + h) * 16 + t] = line ? 0.5f : diag;
        float sc = line ? 0.5f / (1.f - diag) : 1.f;
        for (int j = 0; j < 16; j++)
            g_nds[(((size_t)b * 8 + h) * 16 + t) * 16 + j] = (j == t) ? 0.f : p[t][j] * sc;
    }
}

// ---------------- K10: window value mix (nds @ wv) + LePE conv ----------------
__global__ void k_win_val(const float* __restrict__ wvg,
                          const float* __restrict__ cw, const float* __restrict__ cb,
                          float* __restrict__ wfg) {
    __shared__ float v[16][129];
    __shared__ float p[16][17];
    __shared__ float w9[WDH * 9];
    __shared__ float bi[WDH];
    int h = blockIdx.x & 7, b = blockIdx.x >> 3;
    int t = threadIdx.x;
    for (int i = t; i < 2048; i += 256) {
        int row = i >> 7, d = i & 127;
        v[row][d] = wvg[((size_t)b * 16 + row) * 1024 + h * 128 + d];
    }
    p[t >> 4][t & 15] = g_nds[((size_t)b * 8 + h) * 256 + t];
    for (int i = t; i < WDH * 9; i += 256) w9[i] = cw[i];
    if (t < WDH) bi[t] = cb[t];
    __syncthreads();
    for (int e = t; e < 2048; e += 256) {
        int i = e >> 7, d = e & 127;
        float acc = 0.f;
#pragma unroll
        for (int j = 0; j < 16; j++) acc = fmaf(p[i][j], v[j][d], acc);
        int gy = i >> 2, gx = i & 3;
        float ca = bi[d];
#pragma unroll
        for (int dy = -1; dy <= 1; dy++) {
            int ny = gy + dy; if (ny < 0 || ny > 3) continue;
#pragma unroll
            for (int dx = -1; dx <= 1; dx++) {
                int nx = gx + dx; if (nx < 0 || nx > 3) continue;
                ca = fmaf(w9[d * 9 + (dy + 1) * 3 + (dx + 1)], v[ny * 4 + nx][d], ca);
            }
        }
        wfg[((size_t)b * 16 + i) * 1024 + h * 128 + d] = acc + ca;
    }
}

// ---------------- K12: diag-scale + add + inverse shuffle + residual ----------------
__global__ void k_final(const float* __restrict__ x, const float* __restrict__ pfo,
                        const float* __restrict__ wfo, float* __restrict__ out) {
    __shared__ float sa[512], sb[512], sds[8];
    int blk = blockIdx.x;                        // b*512 + win*32 + sy
    int sy = blk & 31, win = (blk >> 5) & 15, b = blk >> 9;
    int wy = win >> 2, wx = win & 3;
    int t = threadIdx.x;
    size_t base = ((size_t)b * 16 + win) * WD + (size_t)sy * 512;
    for (int e = t; e < 512; e += 256) { sa[e] = pfo[base + e]; sb[e] = wfo[base + e]; }
    if (t < 8) sds[t] = g_dsdiag[((size_t)b * 8 + t) * 16 + win];
    __syncthreads();
    int y = wy * WS + sy;
    for (int i = t; i < 512; i += 256) {
        int c = i >> 5, sx = i & 31;
        int e = sx * 16 + c;
        int hh = (sy * 32 + sx) >> 7;
        size_t xi = ((size_t)(b * nC + c) * SZ + y) * SZ + wx * WS + sx;
        out[xi] = x[xi] + sds[hh] * sa[e] + sb[e];
    }
}

// ---------------- launch ----------------
extern "C" void kernel_launch(void* const* d_in, const int* in_sizes, int n_in,
                              void* d_out, int out_size) {
    const float* x        = (const float*)d_in[0];
    const float* pn_g     = (const float*)d_in[1];
    const float* pn_b     = (const float*)d_in[2];
    const float* Wqk_p    = (const float*)d_in[3];
    const float* Wv_p     = (const float*)d_in[4];
    const float* conv_p_w = (const float*)d_in[5];
    const float* conv_p_b = (const float*)d_in[6];
    const float* Wout_p   = (const float*)d_in[7];
    const float* pln_g    = (const float*)d_in[8];
    const float* pln_b    = (const float*)d_in[9];
    const float* Wqk_w    = (const float*)d_in[10];
    const float* wn_g     = (const float*)d_in[11];
    const float* wn_b     = (const float*)d_in[12];
    const float* Wv_w     = (const float*)d_in[13];
    const float* conv_w_w = (const float*)d_in[14];
    const float* conv_w_b = (const float*)d_in[15];
    const float* Wout_w   = (const float*)d_in[16];
    float* out = (float*)d_out;

    float *bufA, *bufB, *bufC, *bufD, *pl, *qkw, *wv, *wf;
    cudaGetSymbolAddress((void**)&bufA, g_bufA);
    cudaGetSymbolAddress((void**)&bufB, g_bufB);
    cudaGetSymbolAddress((void**)&bufC, g_bufC);
    cudaGetSymbolAddress((void**)&bufD, g_bufD);
    cudaGetSymbolAddress((void**)&pl,   g_pl);
    cudaGetSymbolAddress((void**)&qkw,  g_qkw);
    cudaGetSymbolAddress((void**)&wv,   g_wv);
    cudaGetSymbolAddress((void**)&wf,   g_wf);

    // alias map (lifetimes verified):
    float* fl   = bufA;   // LN'd patch feats
    float* qk   = bufB;   // patch q|k (dead after k_patch_attn)
    float* pv   = bufC;
    float* pf   = bufA;   // reuse: fl dead after Wqk/Wv GEMMs
    float* pfo  = bufB;   // reuse: qk dead after k_patch_attn
    float* xwln = bufD;
    float* wfo  = bufD;   // reuse: xwln dead after Wv_w GEMM

    cudaFuncSetAttribute(k_xw_ln, cudaFuncAttributeMaxDynamicSharedMemorySize, WD * 4);

    // ---- patch (intra-window) branch ----
    k_patch_ln<<<nB * NWIN * NPAT, 256>>>(x, pn_g, pn_b, fl);
    sgemm<128,128,16,8,8><<<dim3(2048/128, 16384/128), 256>>>(fl, Wqk_p, qk, 16384, 2048, 1024);
    sgemm<128,128,16,8,8><<<dim3(1024/128, 16384/128), 256>>>(fl, Wv_p,  pv, 16384, 1024, 1024);
    k_patch_attn<<<nB * NWIN * nH, 256>>>(qk, pv, conv_p_w, conv_p_b, pf);
    sgemm<128,128,16,8,8><<<dim3(1024/128, 16384/128), 256>>>(pf, Wout_p, pfo, 16384, 1024, 1024);

    // ---- window (inter-window) branch ----
    k_pool_ln<<<nB * NWIN, 256>>>(x, pln_g, pln_b, pl);
    sgemm<128,128,16,8,8><<<dim3(2048/128, 1024/128), 256>>>(pl, Wqk_w, qkw, 1024, 2048, 1024);
    k_win_probs<<<nB * nH, 256>>>(qkw);
    k_xw_ln<<<nB * NWIN, 256, WD * 4>>>(x, wn_g, wn_b, xwln);
    sgemm<64,64,16,4,4><<<dim3(1024/64, 1024/64), 256>>>(xwln, Wv_w, wv, 1024, 1024, 16384);
    k_win_val<<<nB * nH, 256>>>(wv, conv_w_w, conv_w_b, wf);
    sgemm<128,128,16,8,8><<<dim3(16384/128, 1024/128), 256>>>(wf, Wout_w, wfo, 1024, 16384, 1024);

    // ---- fuse diag-scale + residual + inverse shuffle ----
    k_final<<<nB * NWIN * WS, 256>>>(x, pfo, wfo, out);
}